// round 13
// baseline (speedup 1.0000x reference)
#include <cuda_runtime.h>
#include <cuda_fp16.h>
#include <cstdint>

// Problem-size maxima (fixed problem: N=200000, E=6400000, G=20000)
#define MAX_N 200000
#define MAX_G 20000

// Read-only gather table: 5 fp16 attrs + pad = 16B/node
__device__ __align__(128) __half g_attr16[MAX_N * 8];
// Atomic-only accumulator, ONE 32B record/node:
//   halves 0-7 : msg dims 0-7 (v4.f16x2 RED)
//   halves 8-9 : msg dims 8-9 (scalar f16x2 RED, same 32B sector)
__device__ __align__(128) __half g_acc[MAX_N * 16];
__device__ __align__(16) float g_accG[MAX_G * 8];   // per-graph pooled sum (5 used)

// Edge-MLP weights in constant memory -> uniform/constant port (off l1tex).
// layout: [0..139] w_mpl row-major [14][10], [140..149] b_mpl
__constant__ float c_wmpl[152];

// ---------------- vector reductions ----------------
__device__ __forceinline__ void red_add_v4_f16x2(void* p, unsigned h0, unsigned h1,
                                                 unsigned h2, unsigned h3) {
    asm volatile("red.global.add.noftz.v4.f16x2 [%0], {%1,%2,%3,%4};"
                 :: "l"(p), "r"(h0), "r"(h1), "r"(h2), "r"(h3) : "memory");
}
__device__ __forceinline__ void red_add_f16x2(void* p, unsigned h) {
    asm volatile("red.global.add.noftz.f16x2 [%0], %1;"
                 :: "l"(p), "r"(h) : "memory");
}
__device__ __forceinline__ void red_add_v4(float* p, float a, float b, float c, float d) {
    asm volatile("red.global.add.v4.f32 [%0], {%1,%2,%3,%4};"
                 :: "l"(p), "f"(a), "f"(b), "f"(c), "f"(d) : "memory");
}
__device__ __forceinline__ void red_add_f(float* p, float a) {
    asm volatile("red.global.add.f32 [%0], %1;"
                 :: "l"(p), "f"(a) : "memory");
}

// Gather load with L1 evict_last (keep attr table slice resident in L1)
__device__ __forceinline__ uint4 ldg_evict_last(const uint4* p) {
    uint4 v;
    asm("ld.global.nc.L1::evict_last.v4.u32 {%0,%1,%2,%3}, [%4];"
        : "=r"(v.x), "=r"(v.y), "=r"(v.z), "=r"(v.w) : "l"(p));
    return v;
}

// ---------------- kernel 1: repack attrs + zero accumulators (+accG) ----------------
// Coalesced: block stages its 256 nodes' 1280 contiguous floats through smem,
// reads back at stride 5 (conflict-free: gcd(5,32)=1).
__global__ void prep_kernel(const float* __restrict__ node_attr,
                            __half* __restrict__ attr16,
                            __half* __restrict__ acc,
                            float* __restrict__ accG,
                            int N, int G8) {
    __shared__ float sa[256 * 5];
    int t = threadIdx.x;
    int base = blockIdx.x * 256;
    int nfl = (N - base) * 5;
    if (nfl > 1280) nfl = 1280;
    const float* srcp = node_attr + (size_t)base * 5;
    for (int i = t; i < nfl; i += 256) sa[i] = srcp[i];
    __syncthreads();

    int n = base + t;
    if (n < G8) accG[n] = 0.f;          // fold accG memset in (G8 < N)
    if (n >= N) return;

    float a0 = sa[t * 5 + 0];
    float a1 = sa[t * 5 + 1];
    float a2 = sa[t * 5 + 2];
    float a3 = sa[t * 5 + 3];
    float a4 = sa[t * 5 + 4];
    __half2 h01 = __floats2half2_rn(a0, a1);
    __half2 h23 = __floats2half2_rn(a2, a3);
    __half2 h4x = __floats2half2_rn(a4, 0.f);
    uint4 rec;
    rec.x = *(const unsigned*)&h01;
    rec.y = *(const unsigned*)&h23;
    rec.z = *(const unsigned*)&h4x;
    rec.w = 0u;
    ((uint4*)attr16)[n] = rec;
    uint4 z = {0u, 0u, 0u, 0u};
    ((uint4*)acc)[n * 2 + 0] = z;
    ((uint4*)acc)[n * 2 + 1] = z;
}

// ---------------- kernel 2: edge kernel ----------------
// msg = relu([a_src, a_dst, e] @ W + b); dims0-7 -> v4.f16x2 RED, dims8-9 ->
// scalar f16x2 RED (ReLU-sparsity elision). Streaming operands use evict-first
// (__ldcs); gathers use L1 evict_last. Block=128 for finer wave quantization.
__global__ void edge_kernel(const int* __restrict__ ei,          // [2][E]
                            const float4* __restrict__ ea4,      // [E] (D_EDGE=4)
                            const uint4* __restrict__ attr16,    // [N] 16B fp16 records
                            __half* __restrict__ acc,            // [N] 32B records
                            int E) {
    int e = blockIdx.x * blockDim.x + threadIdx.x;
    if (e >= E) return;

    int src = __ldcs(ei + e);
    int dst = __ldcs(ei + E + e);

    uint4 ra = ldg_evict_last(attr16 + src);   // divergent gather
    uint4 rb = ldg_evict_last(attr16 + dst);   // divergent gather
    float4 ea = __ldcs(ea4 + e);               // coalesced, use-once

    float x[14];
    {
        float2 p;
        p = __half22float2(*(const __half2*)&ra.x); x[0] = p.x; x[1] = p.y;
        p = __half22float2(*(const __half2*)&ra.y); x[2] = p.x; x[3] = p.y;
        p = __half22float2(*(const __half2*)&ra.z); x[4] = p.x;
        p = __half22float2(*(const __half2*)&rb.x); x[5] = p.x; x[6] = p.y;
        p = __half22float2(*(const __half2*)&rb.y); x[7] = p.x; x[8] = p.y;
        p = __half22float2(*(const __half2*)&rb.z); x[9] = p.x;
    }
    x[10] = ea.x; x[11] = ea.y; x[12] = ea.z; x[13] = ea.w;

    float m[10];
#pragma unroll
    for (int j = 0; j < 10; j++) m[j] = c_wmpl[140 + j];
#pragma unroll
    for (int i = 0; i < 14; i++) {
        float xi = x[i];
#pragma unroll
        for (int j = 0; j < 10; j++) m[j] = fmaf(xi, c_wmpl[i * 10 + j], m[j]);
    }
#pragma unroll
    for (int j = 0; j < 10; j++) m[j] = fmaxf(m[j], 0.f);

    __half2 p0 = __floats2half2_rn(m[0], m[1]);
    __half2 p1 = __floats2half2_rn(m[2], m[3]);
    __half2 p2 = __floats2half2_rn(m[4], m[5]);
    __half2 p3 = __floats2half2_rn(m[6], m[7]);
    __half2 p4 = __floats2half2_rn(m[8], m[9]);

    __half* ap = acc + (size_t)dst * 16;   // 32B-aligned record

    float s07 = ((m[0] + m[1]) + (m[2] + m[3])) + ((m[4] + m[5]) + (m[6] + m[7]));
    if (s07 > 0.f)
        red_add_v4_f16x2(ap,
                         *(const unsigned*)&p0, *(const unsigned*)&p1,
                         *(const unsigned*)&p2, *(const unsigned*)&p3);
    if (m[8] + m[9] > 0.f)
        red_add_f16x2(ap + 8, *(const unsigned*)&p4);
}

// ---------------- kernel 3: node MLP + warp-aggregated pool ----------------
// batch is SORTED -> segmented warp reduction; only segment leaders issue
// accG REDs.
__global__ void node_kernel(const __half* __restrict__ acc,
                            const int* __restrict__ batch,
                            const float* __restrict__ w1, const float* __restrict__ b1,
                            const float* __restrict__ w2, const float* __restrict__ b2,
                            float* __restrict__ accG,
                            int N) {
    __shared__ float s[165];  // w1(100) b1(10) w2(50) b2(5)
    int t = threadIdx.x;
    if (t < 100)       s[t] = w1[t];
    else if (t < 110)  s[t] = b1[t - 100];
    else if (t < 160)  s[t] = w2[t - 110];
    else if (t < 165)  s[t] = b2[t - 160];
    __syncthreads();

    int n = blockIdx.x * blockDim.x + t;
    bool active = n < N;

    float h2[5] = {0.f, 0.f, 0.f, 0.f, 0.f};
    int g = -1;

    if (active) {
        uint4 r0 = __ldcs((const uint4*)(acc + (size_t)n * 16));
        uint4 r1 = __ldcs((const uint4*)(acc + (size_t)n * 16) + 1);

        float x[10];
        {
            float2 u;
            u = __half22float2(*(const __half2*)&r0.x); x[0] = u.x; x[1] = u.y;
            u = __half22float2(*(const __half2*)&r0.y); x[2] = u.x; x[3] = u.y;
            u = __half22float2(*(const __half2*)&r0.z); x[4] = u.x; x[5] = u.y;
            u = __half22float2(*(const __half2*)&r0.w); x[6] = u.x; x[7] = u.y;
            u = __half22float2(*(const __half2*)&r1.x); x[8] = u.x; x[9] = u.y;
        }

        float h1[10];
#pragma unroll
        for (int j = 0; j < 10; j++) {
            float v = s[100 + j];  // b1
#pragma unroll
            for (int i = 0; i < 10; i++) v = fmaf(x[i], s[i * 10 + j], v);
            h1[j] = fmaxf(v, 0.f);
        }

#pragma unroll
        for (int j = 0; j < 5; j++) {
            float v = s[160 + j];  // b2
#pragma unroll
            for (int i = 0; i < 10; i++) v = fmaf(h1[i], s[110 + i * 5 + j], v);
            h2[j] = fmaxf(v, 0.f);
        }
        g = __ldcs(batch + n);
    }

    // segmented warp reduction over contiguous equal-g lanes
    unsigned eq = __match_any_sync(0xffffffffu, g);
    int lane = t & 31;
    int hi = 31 - __clz(eq);   // highest lane of this segment
#pragma unroll
    for (int off = 1; off < 32; off <<= 1) {
#pragma unroll
        for (int j = 0; j < 5; j++) {
            float v = __shfl_down_sync(0xffffffffu, h2[j], off);
            if (lane + off <= hi) h2[j] += v;
        }
    }
    bool leader = (lane == __ffs(eq) - 1);
    if (leader && active) {
        float* gp = accG + (size_t)g * 8;   // 32B stride -> 16B aligned
        if (((h2[0] + h2[1]) + (h2[2] + h2[3])) > 0.f)
            red_add_v4(gp, h2[0], h2[1], h2[2], h2[3]);
        if (h2[4] > 0.f)
            red_add_f(gp + 4, h2[4]);
    }
}

// ---------------- kernel 4: graph head (no smem, 64-thread blocks) ----------------
__global__ void graph_kernel(const float* __restrict__ accG,
                             const float* __restrict__ w3, const float* __restrict__ b3,
                             const float* __restrict__ w4, const float* __restrict__ b4,
                             float* __restrict__ out,
                             int G) {
    int g = blockIdx.x * blockDim.x + threadIdx.x;
    if (g >= G) return;

    float4 v0 = *(const float4*)(accG + (size_t)g * 8);
    float x4 = accG[(size_t)g * 8 + 4];
    float x[5] = {v0.x, v0.y, v0.z, v0.w, x4};

    float o = __ldg(b4);
#pragma unroll
    for (int j = 0; j < 5; j++) {
        float v = __ldg(b3 + j);
#pragma unroll
        for (int i = 0; i < 5; i++) v = fmaf(x[i], __ldg(w3 + i * 5 + j), v);
        o = fmaf(fmaxf(v, 0.f), __ldg(w4 + j), o);
    }
    out[g] = o;
}

// ---------------- launch ----------------
extern "C" void kernel_launch(void* const* d_in, const int* in_sizes, int n_in,
                              void* d_out, int out_size) {
    const int*   ei        = (const int*)d_in[0];
    const float* node_attr = (const float*)d_in[1];
    const float* edge_attr = (const float*)d_in[2];
    const int*   batch     = (const int*)d_in[3];

    // num_graphs may or may not be materialized as a scalar input at index 4
    int base = (n_in >= 15 && in_sizes[4] == 1) ? 5 : 4;
    const float* w_mpl = (const float*)d_in[base + 0];
    const float* b_mpl = (const float*)d_in[base + 1];
    const float* w1    = (const float*)d_in[base + 2];
    const float* b1    = (const float*)d_in[base + 3];
    const float* w2    = (const float*)d_in[base + 4];
    const float* b2    = (const float*)d_in[base + 5];
    const float* w3    = (const float*)d_in[base + 6];
    const float* b3    = (const float*)d_in[base + 7];
    const float* w4    = (const float*)d_in[base + 8];
    const float* b4    = (const float*)d_in[base + 9];

    int E = in_sizes[0] / 2;
    int N = in_sizes[1] / 5;
    int G = out_size;

    __half *attr16, *acc;
    float *accG;
    cudaGetSymbolAddress((void**)&attr16, g_attr16);
    cudaGetSymbolAddress((void**)&acc, g_acc);
    cudaGetSymbolAddress((void**)&accG, g_accG);

    // stage edge-MLP weights into constant memory (D2D async, graph-legal)
    float* cW;
    cudaGetSymbolAddress((void**)&cW, c_wmpl);
    cudaMemcpyAsync(cW, w_mpl, 140 * sizeof(float), cudaMemcpyDeviceToDevice, 0);
    cudaMemcpyAsync(cW + 140, b_mpl, 10 * sizeof(float), cudaMemcpyDeviceToDevice, 0);

    prep_kernel<<<(N + 255) / 256, 256>>>(node_attr, attr16, acc, accG, N, G * 8);
    edge_kernel<<<(E + 127) / 128, 128>>>(ei, (const float4*)edge_attr,
                                          (const uint4*)attr16, acc, E);
    node_kernel<<<(N + 255) / 256, 256>>>(acc, batch, w1, b1, w2, b2, accG, N);
    graph_kernel<<<(G + 63) / 64, 64>>>(accG, w3, b3, w4, b4, (float*)d_out, G);
}

// round 14
// speedup vs baseline: 1.0164x; 1.0164x over previous
#include <cuda_runtime.h>
#include <cuda_fp16.h>
#include <cstdint>

// Problem-size maxima (fixed problem: N=200000, E=6400000, G=20000)
#define MAX_N 200000
#define MAX_G 20000

// Read-only gather table: 5 fp16 attrs + pad = 16B/node
__device__ __align__(128) __half g_attr16[MAX_N * 8];
// Atomic-only accumulator, ONE 32B record/node:
//   halves 0-7 : msg dims 0-7 (v4.f16x2 RED)
//   halves 8-9 : msg dims 8-9 (scalar f16x2 RED, same 32B sector)
__device__ __align__(128) __half g_acc[MAX_N * 16];
__device__ __align__(16) float g_accG[MAX_G * 8];   // per-graph pooled sum (5 used)

// Edge-MLP weights in constant memory -> uniform/constant port (off l1tex).
// layout: [0..139] w_mpl row-major [14][10]
__constant__ float c_wmpl[144];

// ---------------- vector reductions ----------------
__device__ __forceinline__ void red_add_v4_f16x2(void* p, unsigned h0, unsigned h1,
                                                 unsigned h2, unsigned h3) {
    asm volatile("red.global.add.noftz.v4.f16x2 [%0], {%1,%2,%3,%4};"
                 :: "l"(p), "r"(h0), "r"(h1), "r"(h2), "r"(h3) : "memory");
}
__device__ __forceinline__ void red_add_f16x2(void* p, unsigned h) {
    asm volatile("red.global.add.noftz.f16x2 [%0], %1;"
                 :: "l"(p), "r"(h) : "memory");
}
__device__ __forceinline__ void red_add_v4(float* p, float a, float b, float c, float d) {
    asm volatile("red.global.add.v4.f32 [%0], {%1,%2,%3,%4};"
                 :: "l"(p), "f"(a), "f"(b), "f"(c), "f"(d) : "memory");
}
__device__ __forceinline__ void red_add_f(float* p, float a) {
    asm volatile("red.global.add.f32 [%0], %1;"
                 :: "l"(p), "f"(a) : "memory");
}

// Gather load with L1 evict_last (keep attr table slice resident in L1)
__device__ __forceinline__ uint4 ldg_evict_last(const uint4* p) {
    uint4 v;
    asm("ld.global.nc.L1::evict_last.v4.u32 {%0,%1,%2,%3}, [%4];"
        : "=r"(v.x), "=r"(v.y), "=r"(v.z), "=r"(v.w) : "l"(p));
    return v;
}

// ---------------- kernel 1: repack attrs + zero accumulators (+accG) ----------------
__global__ void prep_kernel(const float* __restrict__ node_attr,
                            __half* __restrict__ attr16,
                            __half* __restrict__ acc,
                            float* __restrict__ accG,
                            int N, int G8) {
    int n = blockIdx.x * blockDim.x + threadIdx.x;
    if (n < G8) accG[n] = 0.f;          // fold accG memset in (G8 < N)
    if (n < N) {
        float a0 = node_attr[(size_t)n * 5 + 0];
        float a1 = node_attr[(size_t)n * 5 + 1];
        float a2 = node_attr[(size_t)n * 5 + 2];
        float a3 = node_attr[(size_t)n * 5 + 3];
        float a4 = node_attr[(size_t)n * 5 + 4];
        __half2 h01 = __floats2half2_rn(a0, a1);
        __half2 h23 = __floats2half2_rn(a2, a3);
        __half2 h4x = __floats2half2_rn(a4, 0.f);
        uint4 rec;
        rec.x = *(const unsigned*)&h01;
        rec.y = *(const unsigned*)&h23;
        rec.z = *(const unsigned*)&h4x;
        rec.w = 0u;
        ((uint4*)attr16)[n] = rec;
        uint4 z = {0u, 0u, 0u, 0u};
        ((uint4*)acc)[n * 2 + 0] = z;
        ((uint4*)acc)[n * 2 + 1] = z;
    }
    cudaTriggerProgrammaticLaunchCompletion();
}

// ---------------- kernel 2: edge kernel (PDL consumer of prep) ----------------
// Streaming ei/ea loads run BEFORE the grid dependency sync (they don't
// depend on prep); gathers + REDs after.
__global__ void edge_kernel(const int* __restrict__ ei,          // [2][E]
                            const float4* __restrict__ ea4,      // [E] (D_EDGE=4)
                            const uint4* __restrict__ attr16,    // [N] 16B fp16 records
                            __half* __restrict__ acc,            // [N] 32B records
                            const float* __restrict__ b_mpl,     // [10]
                            int E) {
    int e = blockIdx.x * blockDim.x + threadIdx.x;
    if (e < E) {
        // dependency-free prologue (overlaps prep's tail under PDL)
        int src = __ldcs(ei + e);
        int dst = __ldcs(ei + E + e);
        float4 ea = __ldcs(ea4 + e);

        float m[10];
#pragma unroll
        for (int j = 0; j < 10; j++) m[j] = __ldg(b_mpl + j);
#pragma unroll
        for (int j = 0; j < 10; j++) {
            m[j] = fmaf(ea.x, c_wmpl[100 + j], m[j]);
            m[j] = fmaf(ea.y, c_wmpl[110 + j], m[j]);
            m[j] = fmaf(ea.z, c_wmpl[120 + j], m[j]);
            m[j] = fmaf(ea.w, c_wmpl[130 + j], m[j]);
        }

        cudaGridDependencySynchronize();   // wait for prep's attr16/acc

        uint4 ra = ldg_evict_last(attr16 + src);   // divergent gather
        uint4 rb = ldg_evict_last(attr16 + dst);   // divergent gather

        float x[10];
        {
            float2 p;
            p = __half22float2(*(const __half2*)&ra.x); x[0] = p.x; x[1] = p.y;
            p = __half22float2(*(const __half2*)&ra.y); x[2] = p.x; x[3] = p.y;
            p = __half22float2(*(const __half2*)&ra.z); x[4] = p.x;
            p = __half22float2(*(const __half2*)&rb.x); x[5] = p.x; x[6] = p.y;
            p = __half22float2(*(const __half2*)&rb.y); x[7] = p.x; x[8] = p.y;
            p = __half22float2(*(const __half2*)&rb.z); x[9] = p.x;
        }
#pragma unroll
        for (int i = 0; i < 10; i++) {
            float xi = x[i];
#pragma unroll
            for (int j = 0; j < 10; j++) m[j] = fmaf(xi, c_wmpl[i * 10 + j], m[j]);
        }
#pragma unroll
        for (int j = 0; j < 10; j++) m[j] = fmaxf(m[j], 0.f);

        __half2 p0 = __floats2half2_rn(m[0], m[1]);
        __half2 p1 = __floats2half2_rn(m[2], m[3]);
        __half2 p2 = __floats2half2_rn(m[4], m[5]);
        __half2 p3 = __floats2half2_rn(m[6], m[7]);
        __half2 p4 = __floats2half2_rn(m[8], m[9]);

        __half* ap = acc + (size_t)dst * 16;   // 32B-aligned record

        float s07 = ((m[0] + m[1]) + (m[2] + m[3])) + ((m[4] + m[5]) + (m[6] + m[7]));
        if (s07 > 0.f)
            red_add_v4_f16x2(ap,
                             *(const unsigned*)&p0, *(const unsigned*)&p1,
                             *(const unsigned*)&p2, *(const unsigned*)&p3);
        if (m[8] + m[9] > 0.f)
            red_add_f16x2(ap + 8, *(const unsigned*)&p4);
    } else {
        cudaGridDependencySynchronize();
    }
    cudaTriggerProgrammaticLaunchCompletion();
}

// ---------------- kernel 3: node MLP + warp-aggregated pool (PDL consumer) ----------------
__global__ void node_kernel(const __half* __restrict__ acc,
                            const int* __restrict__ batch,
                            const float* __restrict__ w1, const float* __restrict__ b1,
                            const float* __restrict__ w2, const float* __restrict__ b2,
                            float* __restrict__ accG,
                            int N) {
    __shared__ float s[165];  // w1(100) b1(10) w2(50) b2(5)
    int t = threadIdx.x;
    if (t < 100)       s[t] = w1[t];
    else if (t < 110)  s[t] = b1[t - 100];
    else if (t < 160)  s[t] = w2[t - 110];
    else if (t < 165)  s[t] = b2[t - 160];

    int n = blockIdx.x * blockDim.x + t;
    bool active = n < N;
    int g = active ? batch[n] : -1;       // independent of edge results

    __syncthreads();
    cudaGridDependencySynchronize();      // wait for edge's acc REDs

    float h2[5] = {0.f, 0.f, 0.f, 0.f, 0.f};

    if (active) {
        uint4 r0 = __ldcs((const uint4*)(acc + (size_t)n * 16));
        uint4 r1 = __ldcs((const uint4*)(acc + (size_t)n * 16) + 1);

        float x[10];
        {
            float2 u;
            u = __half22float2(*(const __half2*)&r0.x); x[0] = u.x; x[1] = u.y;
            u = __half22float2(*(const __half2*)&r0.y); x[2] = u.x; x[3] = u.y;
            u = __half22float2(*(const __half2*)&r0.z); x[4] = u.x; x[5] = u.y;
            u = __half22float2(*(const __half2*)&r0.w); x[6] = u.x; x[7] = u.y;
            u = __half22float2(*(const __half2*)&r1.x); x[8] = u.x; x[9] = u.y;
        }

        float h1[10];
#pragma unroll
        for (int j = 0; j < 10; j++) {
            float v = s[100 + j];  // b1
#pragma unroll
            for (int i = 0; i < 10; i++) v = fmaf(x[i], s[i * 10 + j], v);
            h1[j] = fmaxf(v, 0.f);
        }

#pragma unroll
        for (int j = 0; j < 5; j++) {
            float v = s[160 + j];  // b2
#pragma unroll
            for (int i = 0; i < 10; i++) v = fmaf(h1[i], s[110 + i * 5 + j], v);
            h2[j] = fmaxf(v, 0.f);
        }
    }

    // segmented warp reduction over contiguous equal-g lanes (batch sorted)
    unsigned eq = __match_any_sync(0xffffffffu, g);
    int lane = t & 31;
    int hi = 31 - __clz(eq);
#pragma unroll
    for (int off = 1; off < 32; off <<= 1) {
#pragma unroll
        for (int j = 0; j < 5; j++) {
            float v = __shfl_down_sync(0xffffffffu, h2[j], off);
            if (lane + off <= hi) h2[j] += v;
        }
    }
    bool leader = (lane == __ffs(eq) - 1);
    if (leader && active) {
        float* gp = accG + (size_t)g * 8;
        if (((h2[0] + h2[1]) + (h2[2] + h2[3])) > 0.f)
            red_add_v4(gp, h2[0], h2[1], h2[2], h2[3]);
        if (h2[4] > 0.f)
            red_add_f(gp + 4, h2[4]);
    }
    cudaTriggerProgrammaticLaunchCompletion();
}

// ---------------- kernel 4: graph head (PDL consumer) ----------------
__global__ void graph_kernel(const float* __restrict__ accG,
                             const float* __restrict__ w3, const float* __restrict__ b3,
                             const float* __restrict__ w4, const float* __restrict__ b4,
                             float* __restrict__ out,
                             int G) {
    int g = blockIdx.x * blockDim.x + threadIdx.x;

    // dependency-free prologue: preload weights
    float rw3[25], rb3[5], rw4[5];
#pragma unroll
    for (int i = 0; i < 25; i++) rw3[i] = __ldg(w3 + i);
#pragma unroll
    for (int i = 0; i < 5; i++) rb3[i] = __ldg(b3 + i);
#pragma unroll
    for (int i = 0; i < 5; i++) rw4[i] = __ldg(w4 + i);
    float rb4 = __ldg(b4);

    cudaGridDependencySynchronize();      // wait for node's accG REDs

    if (g >= G) return;

    float4 v0 = *(const float4*)(accG + (size_t)g * 8);
    float x4 = accG[(size_t)g * 8 + 4];
    float x[5] = {v0.x, v0.y, v0.z, v0.w, x4};

    float o = rb4;
#pragma unroll
    for (int j = 0; j < 5; j++) {
        float v = rb3[j];
#pragma unroll
        for (int i = 0; i < 5; i++) v = fmaf(x[i], rw3[i * 5 + j], v);
        o = fmaf(fmaxf(v, 0.f), rw4[j], o);
    }
    out[g] = o;
}

// ---------------- launch ----------------
template <typename... Args>
static void launch_pdl(void (*kern)(Args...), dim3 grid, dim3 block, Args... args) {
    cudaLaunchConfig_t cfg = {};
    cfg.gridDim = grid;
    cfg.blockDim = block;
    cfg.stream = 0;
    cudaLaunchAttribute attr[1];
    attr[0].id = cudaLaunchAttributeProgrammaticStreamSerialization;
    attr[0].val.programmaticStreamSerializationAllowed = 1;
    cfg.attrs = attr;
    cfg.numAttrs = 1;
    cudaLaunchKernelEx(&cfg, kern, args...);
}

extern "C" void kernel_launch(void* const* d_in, const int* in_sizes, int n_in,
                              void* d_out, int out_size) {
    const int*   ei        = (const int*)d_in[0];
    const float* node_attr = (const float*)d_in[1];
    const float* edge_attr = (const float*)d_in[2];
    const int*   batch     = (const int*)d_in[3];

    // num_graphs may or may not be materialized as a scalar input at index 4
    int base = (n_in >= 15 && in_sizes[4] == 1) ? 5 : 4;
    const float* w_mpl = (const float*)d_in[base + 0];
    const float* b_mpl = (const float*)d_in[base + 1];
    const float* w1    = (const float*)d_in[base + 2];
    const float* b1    = (const float*)d_in[base + 3];
    const float* w2    = (const float*)d_in[base + 4];
    const float* b2    = (const float*)d_in[base + 5];
    const float* w3    = (const float*)d_in[base + 6];
    const float* b3    = (const float*)d_in[base + 7];
    const float* w4    = (const float*)d_in[base + 8];
    const float* b4    = (const float*)d_in[base + 9];

    int E = in_sizes[0] / 2;
    int N = in_sizes[1] / 5;
    int G = out_size;

    __half *attr16, *acc;
    float *accG;
    cudaGetSymbolAddress((void**)&attr16, g_attr16);
    cudaGetSymbolAddress((void**)&acc, g_acc);
    cudaGetSymbolAddress((void**)&accG, g_accG);

    // stage edge-MLP weight matrix into constant memory (bias stays in gmem)
    float* cW;
    cudaGetSymbolAddress((void**)&cW, c_wmpl);
    cudaMemcpyAsync(cW, w_mpl, 140 * sizeof(float), cudaMemcpyDeviceToDevice, 0);

    prep_kernel<<<(N + 255) / 256, 256>>>(node_attr, attr16, acc, accG, N, G * 8);
    launch_pdl(edge_kernel, dim3((E + 255) / 256), dim3(256),
               ei, (const float4*)edge_attr, (const uint4*)attr16, acc, b_mpl, E);
    launch_pdl(node_kernel, dim3((N + 255) / 256), dim3(256),
               (const __half*)acc, batch, w1, b1, w2, b2, accG, N);
    launch_pdl(graph_kernel, dim3((G + 63) / 64), dim3(64),
               (const float*)accG, w3, b3, w4, b4, (float*)d_out, G);
}

// round 15
// speedup vs baseline: 1.0383x; 1.0215x over previous
#include <cuda_runtime.h>
#include <cuda_fp16.h>
#include <cstdint>

// Problem-size maxima (fixed problem: N=200000, E=6400000, G=20000)
#define MAX_N 200000
#define MAX_G 20000

// Read-only gather table: 5 fp16 attrs + pad = 16B/node
__device__ __align__(128) __half g_attr16[MAX_N * 8];
// Atomic-only accumulator, ONE 32B record/node:
//   halves 0-7 : msg dims 0-7 (v4.f16x2 RED)
//   halves 8-9 : msg dims 8-9 (scalar f16x2 RED, same 32B sector)
__device__ __align__(128) __half g_acc[MAX_N * 16];
__device__ __align__(16) float g_accG[MAX_G * 8];   // per-graph pooled sum (5 used)

// Edge-MLP weights in constant memory -> uniform/constant port (off l1tex).
// layout: [0..139] w_mpl row-major [14][10], [140..149] b_mpl
__constant__ float c_wmpl[152];

// ---------------- vector reductions ----------------
__device__ __forceinline__ void red_add_v4_f16x2(void* p, unsigned h0, unsigned h1,
                                                 unsigned h2, unsigned h3) {
    asm volatile("red.global.add.noftz.v4.f16x2 [%0], {%1,%2,%3,%4};"
                 :: "l"(p), "r"(h0), "r"(h1), "r"(h2), "r"(h3) : "memory");
}
__device__ __forceinline__ void red_add_f16x2(void* p, unsigned h) {
    asm volatile("red.global.add.noftz.f16x2 [%0], %1;"
                 :: "l"(p), "r"(h) : "memory");
}
__device__ __forceinline__ void red_add_v4(float* p, float a, float b, float c, float d) {
    asm volatile("red.global.add.v4.f32 [%0], {%1,%2,%3,%4};"
                 :: "l"(p), "f"(a), "f"(b), "f"(c), "f"(d) : "memory");
}
__device__ __forceinline__ void red_add_f(float* p, float a) {
    asm volatile("red.global.add.f32 [%0], %1;"
                 :: "l"(p), "f"(a) : "memory");
}

// Gather load with L1 evict_last (keep attr table slice resident in L1)
__device__ __forceinline__ uint4 ldg_evict_last(const uint4* p) {
    uint4 v;
    asm("ld.global.nc.L1::evict_last.v4.u32 {%0,%1,%2,%3}, [%4];"
        : "=r"(v.x), "=r"(v.y), "=r"(v.z), "=r"(v.w) : "l"(p));
    return v;
}

// ---------------- kernel 1: repack attrs + zero accumulators (+accG) ----------------
__global__ void prep_kernel(const float* __restrict__ node_attr,
                            __half* __restrict__ attr16,
                            __half* __restrict__ acc,
                            float* __restrict__ accG,
                            int N, int G8) {
    int n = blockIdx.x * blockDim.x + threadIdx.x;
    if (n < G8) accG[n] = 0.f;          // fold accG memset in (G8 < N)
    if (n < N) {
        float a0 = node_attr[(size_t)n * 5 + 0];
        float a1 = node_attr[(size_t)n * 5 + 1];
        float a2 = node_attr[(size_t)n * 5 + 2];
        float a3 = node_attr[(size_t)n * 5 + 3];
        float a4 = node_attr[(size_t)n * 5 + 4];
        __half2 h01 = __floats2half2_rn(a0, a1);
        __half2 h23 = __floats2half2_rn(a2, a3);
        __half2 h4x = __floats2half2_rn(a4, 0.f);
        uint4 rec;
        rec.x = *(const unsigned*)&h01;
        rec.y = *(const unsigned*)&h23;
        rec.z = *(const unsigned*)&h4x;
        rec.w = 0u;
        ((uint4*)attr16)[n] = rec;
        uint4 z = {0u, 0u, 0u, 0u};
        ((uint4*)acc)[n * 2 + 0] = z;
        ((uint4*)acc)[n * 2 + 1] = z;
    }
    cudaTriggerProgrammaticLaunchCompletion();
}

// ---------------- kernel 2: edge kernel (PDL consumer of prep) ----------------
// Streaming ei/ea loads + edge-feature FMA run BEFORE the grid dependency
// sync; gathers + REDs after. All weights/bias via the constant port.
__global__ void edge_kernel(const int* __restrict__ ei,          // [2][E]
                            const float4* __restrict__ ea4,      // [E] (D_EDGE=4)
                            const uint4* __restrict__ attr16,    // [N] 16B fp16 records
                            __half* __restrict__ acc,            // [N] 32B records
                            int E) {
    int e = blockIdx.x * blockDim.x + threadIdx.x;
    if (e < E) {
        // dependency-free prologue (overlaps prep's tail under PDL)
        int src = __ldcs(ei + e);
        int dst = __ldcs(ei + E + e);
        float4 ea = __ldcs(ea4 + e);

        float m[10];
#pragma unroll
        for (int j = 0; j < 10; j++) m[j] = c_wmpl[140 + j];
#pragma unroll
        for (int j = 0; j < 10; j++) {
            m[j] = fmaf(ea.x, c_wmpl[100 + j], m[j]);
            m[j] = fmaf(ea.y, c_wmpl[110 + j], m[j]);
            m[j] = fmaf(ea.z, c_wmpl[120 + j], m[j]);
            m[j] = fmaf(ea.w, c_wmpl[130 + j], m[j]);
        }

        cudaGridDependencySynchronize();   // wait for prep's attr16/acc

        uint4 ra = ldg_evict_last(attr16 + src);   // divergent gather
        uint4 rb = ldg_evict_last(attr16 + dst);   // divergent gather

        float x[10];
        {
            float2 p;
            p = __half22float2(*(const __half2*)&ra.x); x[0] = p.x; x[1] = p.y;
            p = __half22float2(*(const __half2*)&ra.y); x[2] = p.x; x[3] = p.y;
            p = __half22float2(*(const __half2*)&ra.z); x[4] = p.x;
            p = __half22float2(*(const __half2*)&rb.x); x[5] = p.x; x[6] = p.y;
            p = __half22float2(*(const __half2*)&rb.y); x[7] = p.x; x[8] = p.y;
            p = __half22float2(*(const __half2*)&rb.z); x[9] = p.x;
        }
#pragma unroll
        for (int i = 0; i < 10; i++) {
            float xi = x[i];
#pragma unroll
            for (int j = 0; j < 10; j++) m[j] = fmaf(xi, c_wmpl[i * 10 + j], m[j]);
        }
#pragma unroll
        for (int j = 0; j < 10; j++) m[j] = fmaxf(m[j], 0.f);

        __half2 p0 = __floats2half2_rn(m[0], m[1]);
        __half2 p1 = __floats2half2_rn(m[2], m[3]);
        __half2 p2 = __floats2half2_rn(m[4], m[5]);
        __half2 p3 = __floats2half2_rn(m[6], m[7]);
        __half2 p4 = __floats2half2_rn(m[8], m[9]);

        __half* ap = acc + (size_t)dst * 16;   // 32B-aligned record

        float s07 = ((m[0] + m[1]) + (m[2] + m[3])) + ((m[4] + m[5]) + (m[6] + m[7]));
        if (s07 > 0.f)
            red_add_v4_f16x2(ap,
                             *(const unsigned*)&p0, *(const unsigned*)&p1,
                             *(const unsigned*)&p2, *(const unsigned*)&p3);
        if (m[8] + m[9] > 0.f)
            red_add_f16x2(ap + 8, *(const unsigned*)&p4);
    } else {
        cudaGridDependencySynchronize();
    }
    cudaTriggerProgrammaticLaunchCompletion();
}

// ---------------- kernel 3: node MLP + warp-aggregated pool (PDL consumer) ----------------
__global__ void node_kernel(const __half* __restrict__ acc,
                            const int* __restrict__ batch,
                            const float* __restrict__ w1, const float* __restrict__ b1,
                            const float* __restrict__ w2, const float* __restrict__ b2,
                            float* __restrict__ accG,
                            int N) {
    __shared__ float s[165];  // w1(100) b1(10) w2(50) b2(5)
    int t = threadIdx.x;
    if (t < 100)       s[t] = w1[t];
    else if (t < 110)  s[t] = b1[t - 100];
    else if (t < 160)  s[t] = w2[t - 110];
    else if (t < 165)  s[t] = b2[t - 160];

    int n = blockIdx.x * blockDim.x + t;
    bool active = n < N;
    int g = active ? batch[n] : -1;       // independent of edge results

    __syncthreads();
    cudaGridDependencySynchronize();      // wait for edge's acc REDs

    float h2[5] = {0.f, 0.f, 0.f, 0.f, 0.f};

    if (active) {
        uint4 r0 = __ldcs((const uint4*)(acc + (size_t)n * 16));
        uint4 r1 = __ldcs((const uint4*)(acc + (size_t)n * 16) + 1);

        float x[10];
        {
            float2 u;
            u = __half22float2(*(const __half2*)&r0.x); x[0] = u.x; x[1] = u.y;
            u = __half22float2(*(const __half2*)&r0.y); x[2] = u.x; x[3] = u.y;
            u = __half22float2(*(const __half2*)&r0.z); x[4] = u.x; x[5] = u.y;
            u = __half22float2(*(const __half2*)&r0.w); x[6] = u.x; x[7] = u.y;
            u = __half22float2(*(const __half2*)&r1.x); x[8] = u.x; x[9] = u.y;
        }

        float h1[10];
#pragma unroll
        for (int j = 0; j < 10; j++) {
            float v = s[100 + j];  // b1
#pragma unroll
            for (int i = 0; i < 10; i++) v = fmaf(x[i], s[i * 10 + j], v);
            h1[j] = fmaxf(v, 0.f);
        }

#pragma unroll
        for (int j = 0; j < 5; j++) {
            float v = s[160 + j];  // b2
#pragma unroll
            for (int i = 0; i < 10; i++) v = fmaf(h1[i], s[110 + i * 5 + j], v);
            h2[j] = fmaxf(v, 0.f);
        }
    }

    // segmented warp reduction over contiguous equal-g lanes (batch sorted)
    unsigned eq = __match_any_sync(0xffffffffu, g);
    int lane = t & 31;
    int hi = 31 - __clz(eq);
#pragma unroll
    for (int off = 1; off < 32; off <<= 1) {
#pragma unroll
        for (int j = 0; j < 5; j++) {
            float v = __shfl_down_sync(0xffffffffu, h2[j], off);
            if (lane + off <= hi) h2[j] += v;
        }
    }
    bool leader = (lane == __ffs(eq) - 1);
    if (leader && active) {
        float* gp = accG + (size_t)g * 8;
        if (((h2[0] + h2[1]) + (h2[2] + h2[3])) > 0.f)
            red_add_v4(gp, h2[0], h2[1], h2[2], h2[3]);
        if (h2[4] > 0.f)
            red_add_f(gp + 4, h2[4]);
    }
    cudaTriggerProgrammaticLaunchCompletion();
}

// ---------------- kernel 4: graph head (PDL consumer, slim prologue) ----------------
__global__ void graph_kernel(const float* __restrict__ accG,
                             const float* __restrict__ w3, const float* __restrict__ b3,
                             const float* __restrict__ w4, const float* __restrict__ b4,
                             float* __restrict__ out,
                             int G) {
    int g = blockIdx.x * blockDim.x + threadIdx.x;

    // slim dependency-free prologue: 11 values only (keeps regs low)
    float rb3[5], rw4[5];
#pragma unroll
    for (int i = 0; i < 5; i++) rb3[i] = __ldg(b3 + i);
#pragma unroll
    for (int i = 0; i < 5; i++) rw4[i] = __ldg(w4 + i);
    float rb4 = __ldg(b4);

    cudaGridDependencySynchronize();      // wait for node's accG REDs

    if (g >= G) return;

    float4 v0 = *(const float4*)(accG + (size_t)g * 8);
    float x4 = accG[(size_t)g * 8 + 4];
    float x[5] = {v0.x, v0.y, v0.z, v0.w, x4};

    float o = rb4;
#pragma unroll
    for (int j = 0; j < 5; j++) {
        float v = rb3[j];
#pragma unroll
        for (int i = 0; i < 5; i++) v = fmaf(x[i], __ldg(w3 + i * 5 + j), v);
        o = fmaf(fmaxf(v, 0.f), rw4[j], o);
    }
    out[g] = o;
}

// ---------------- launch ----------------
template <typename... Args>
static void launch_pdl(void (*kern)(Args...), dim3 grid, dim3 block, Args... args) {
    cudaLaunchConfig_t cfg = {};
    cfg.gridDim = grid;
    cfg.blockDim = block;
    cfg.stream = 0;
    cudaLaunchAttribute attr[1];
    attr[0].id = cudaLaunchAttributeProgrammaticStreamSerialization;
    attr[0].val.programmaticStreamSerializationAllowed = 1;
    cfg.attrs = attr;
    cfg.numAttrs = 1;
    cudaLaunchKernelEx(&cfg, kern, args...);
}

extern "C" void kernel_launch(void* const* d_in, const int* in_sizes, int n_in,
                              void* d_out, int out_size) {
    const int*   ei        = (const int*)d_in[0];
    const float* node_attr = (const float*)d_in[1];
    const float* edge_attr = (const float*)d_in[2];
    const int*   batch     = (const int*)d_in[3];

    // num_graphs may or may not be materialized as a scalar input at index 4
    int base = (n_in >= 15 && in_sizes[4] == 1) ? 5 : 4;
    const float* w_mpl = (const float*)d_in[base + 0];
    const float* b_mpl = (const float*)d_in[base + 1];
    const float* w1    = (const float*)d_in[base + 2];
    const float* b1    = (const float*)d_in[base + 3];
    const float* w2    = (const float*)d_in[base + 4];
    const float* b2    = (const float*)d_in[base + 5];
    const float* w3    = (const float*)d_in[base + 6];
    const float* b3    = (const float*)d_in[base + 7];
    const float* w4    = (const float*)d_in[base + 8];
    const float* b4    = (const float*)d_in[base + 9];

    int E = in_sizes[0] / 2;
    int N = in_sizes[1] / 5;
    int G = out_size;

    __half *attr16, *acc;
    float *accG;
    cudaGetSymbolAddress((void**)&attr16, g_attr16);
    cudaGetSymbolAddress((void**)&acc, g_acc);
    cudaGetSymbolAddress((void**)&accG, g_accG);

    // stage edge-MLP weights + bias into constant memory (D2D async)
    float* cW;
    cudaGetSymbolAddress((void**)&cW, c_wmpl);
    cudaMemcpyAsync(cW, w_mpl, 140 * sizeof(float), cudaMemcpyDeviceToDevice, 0);
    cudaMemcpyAsync(cW + 140, b_mpl, 10 * sizeof(float), cudaMemcpyDeviceToDevice, 0);

    prep_kernel<<<(N + 255) / 256, 256>>>(node_attr, attr16, acc, accG, N, G * 8);
    launch_pdl(edge_kernel, dim3((E + 255) / 256), dim3(256),
               ei, (const float4*)edge_attr, (const uint4*)attr16, (__half*)acc, E);
    launch_pdl(node_kernel, dim3((N + 255) / 256), dim3(256),
               (const __half*)acc, batch, w1, b1, w2, b2, (float*)accG, N);
    launch_pdl(graph_kernel, dim3((G + 63) / 64), dim3(64),
               (const float*)accG, w3, b3, w4, b4, (float*)d_out, G);
}